// round 15
// baseline (speedup 1.0000x reference)
#include <cuda_runtime.h>
#include <cstddef>

// SpanRepresentation: out[b, s, :] = concat(x[b,start,:], x[b,end,:], wemb[wid,:])
// B=16, L=512, D=768, W=8, WD=64, NS=4068. Spans ordered by width 1..8, then start.
//
// R15 = R12 (best: one CTA per output row, 128 threads, 4-phase MLP-4 unroll)
// with ONE change: default-policy stores instead of __stcs (evict-first).
// Purpose: test whether evict-first writeback was fragmenting the DRAM write
// stream (eager small writeback bursts -> lower page-hit rate). Every prior
// variant used .cs; this is the last untested axis after L1-path (R14),
// L2-traffic (R8), and write-contiguity (R9) were all ruled out.

constexpr int B    = 16;
constexpr int L    = 512;
constexpr int D    = 768;
constexpr int WD   = 64;
constexpr int NS   = 4068;

constexpr int D4   = D / 4;              // 192
constexpr int WD4  = WD / 4;             // 16
constexpr int ROW4 = (2 * D + WD) / 4;   // 400

__global__ __launch_bounds__(128, 16)
void span_repr_kernel(const float4* __restrict__ x,      // [B, L, D/4]
                      const float4* __restrict__ wemb,   // [8, WD/4]
                      float4* __restrict__ out)          // [B*NS, ROW4]
{
    const int row = blockIdx.x;
    const int b   = row / NS;
    const int s   = row - b * NS;
    const int tid = threadIdx.x;

    // width bucket (block-uniform, 7 compares)
    int wid = 0;
    wid += (s >= 512);
    wid += (s >= 1023);
    wid += (s >= 1533);
    wid += (s >= 2042);
    wid += (s >= 2550);
    wid += (s >= 3057);
    wid += (s >= 3563);
    const int off   = 512 * wid - (wid * (wid - 1)) / 2;  // cumulative span offset
    const int start = s - off;
    const int end   = start + wid;

    const float4* __restrict__ xs = x    + ((size_t)b * L + start) * D4;
    const float4* __restrict__ xe = x    + ((size_t)b * L + end)   * D4;
    const float4* __restrict__ wf = wemb + (size_t)wid * WD4;
    float4* __restrict__ o        = out  + (size_t)row * ROW4;

    // ---- issue all loads first (MLP 4) ----
    const float4 v0 = __ldg(&xs[tid]);                                   // [0,128)
    const float4 v1 = (tid < 64) ? __ldg(&xs[tid + 128])                 // [128,256)
                                 : __ldg(&xe[tid + 128 - D4]);
    const float4 v2 = __ldg(&xe[tid + 256 - D4]);                        // [256,384)
    float4 v3;
    if (tid < WD4) v3 = __ldg(&wf[tid]);                                 // [384,400)

    // ---- store burst: DEFAULT policy (let L2 batch the writeback stream) ----
    o[tid]       = v0;
    o[tid + 128] = v1;
    o[tid + 256] = v2;
    if (tid < WD4) o[tid + 384] = v3;
}

extern "C" void kernel_launch(void* const* d_in, const int* in_sizes, int n_in,
                              void* d_out, int out_size)
{
    const float4* x    = (const float4*)d_in[0];   // [16, 512, 768] fp32
    const float4* wemb = (const float4*)d_in[1];   // [8, 64] fp32
    float4* out        = (float4*)d_out;           // [16, 4068, 1600] fp32

    (void)in_sizes; (void)n_in; (void)out_size;

    dim3 grid(B * NS);   // 65088 CTAs, one output row each
    dim3 block(128);
    span_repr_kernel<<<grid, block>>>(x, wemb, out);
}

// round 16
// speedup vs baseline: 1.0084x; 1.0084x over previous
#include <cuda_runtime.h>
#include <cstddef>

// SpanRepresentation: out[b, s, :] = concat(x[b,start,:], x[b,end,:], wemb[wid,:])
// B=16, L=512, D=768, W=8, WD=64, NS=4068. Spans ordered by width 1..8, then start.
//
// R16 (final): R12 — the best measured variant (one CTA per output row,
// 128 threads, 4-phase MLP-4 unroll, streaming stores) — with a 2D grid
// (NS, B) so b/s come from blockIdx directly, eliminating the per-thread
// integer division row/NS from the CTA prologue.
//
// Evidence across R3..R15: DRAM pins at ~75% (5.9-6.0 TB/s) regardless of
// store ISA (STG/STG.256/TMA), L2 read traffic, write contiguity, MLP, or
// eviction policy — only occupancy/issue concurrency moves it. The output
// write stream is at the B300 pure-write bandwidth ceiling; this kernel is
// at the hardware floor.

constexpr int B    = 16;
constexpr int L    = 512;
constexpr int D    = 768;
constexpr int WD   = 64;
constexpr int NS   = 4068;

constexpr int D4   = D / 4;              // 192
constexpr int WD4  = WD / 4;             // 16
constexpr int ROW4 = (2 * D + WD) / 4;   // 400

__global__ __launch_bounds__(128, 16)
void span_repr_kernel(const float4* __restrict__ x,      // [B, L, D/4]
                      const float4* __restrict__ wemb,   // [8, WD/4]
                      float4* __restrict__ out)          // [B*NS, ROW4]
{
    const int s   = blockIdx.x;          // span index 0..NS-1
    const int b   = blockIdx.y;          // batch index 0..B-1
    const int tid = threadIdx.x;

    // width bucket (block-uniform, 7 compares)
    int wid = 0;
    wid += (s >= 512);
    wid += (s >= 1023);
    wid += (s >= 1533);
    wid += (s >= 2042);
    wid += (s >= 2550);
    wid += (s >= 3057);
    wid += (s >= 3563);
    const int off   = 512 * wid - (wid * (wid - 1)) / 2;  // cumulative span offset
    const int start = s - off;
    const int end   = start + wid;

    const float4* __restrict__ xs = x    + ((size_t)b * L + start) * D4;
    const float4* __restrict__ xe = x    + ((size_t)b * L + end)   * D4;
    const float4* __restrict__ wf = wemb + (size_t)wid * WD4;
    float4* __restrict__ o        = out  + ((size_t)b * NS + s) * ROW4;

    // ---- issue all loads first (MLP 4) ----
    const float4 v0 = __ldg(&xs[tid]);                                   // [0,128)
    const float4 v1 = (tid < 64) ? __ldg(&xs[tid + 128])                 // [128,256)
                                 : __ldg(&xe[tid + 128 - D4]);
    const float4 v2 = __ldg(&xe[tid + 256 - D4]);                        // [256,384)
    float4 v3;
    if (tid < WD4) v3 = __ldg(&wf[tid]);                                 // [384,400)

    // ---- store burst (streaming: output touched once; keep x in L2) ----
    __stcs(&o[tid],        v0);
    __stcs(&o[tid + 128],  v1);
    __stcs(&o[tid + 256],  v2);
    if (tid < WD4) __stcs(&o[tid + 384], v3);
}

extern "C" void kernel_launch(void* const* d_in, const int* in_sizes, int n_in,
                              void* d_out, int out_size)
{
    const float4* x    = (const float4*)d_in[0];   // [16, 512, 768] fp32
    const float4* wemb = (const float4*)d_in[1];   // [8, 64] fp32
    float4* out        = (float4*)d_out;           // [16, 4068, 1600] fp32

    (void)in_sizes; (void)n_in; (void)out_size;

    dim3 grid(NS, B);    // 4068 x 16 = 65088 CTAs, one output row each
    dim3 block(128);
    span_repr_kernel<<<grid, block>>>(x, wemb, out);
}